// round 1
// baseline (speedup 1.0000x reference)
#include <cuda_runtime.h>
#include <math.h>

#define B 8
#define M 64
#define D 256
#define NN 16384

// ---- scratch (device globals; no allocations allowed) ----
__device__ float g_c[B*M*D];          // c (then normalized in place -> cnorm)
__device__ float g_vc[B*M*D];         // vc
__device__ float g_assign[(size_t)B*M*NN];   // assignment [B,M,N] 33.5MB
__device__ float g_colsum[B*M];       // sum_n assignment
__device__ float g_agg[B*M*D];        // av accum, then agg in place

// ---------------------------------------------------------------------------
// zero accumulators (must run every launch: graph replays)
__global__ void k_init() {
    int idx = blockIdx.x * 256 + threadIdx.x;
    if (idx < B*M*D) g_agg[idx] = 0.f;
    if (idx < B*M)   g_colsum[idx] = 0.f;
}

// ---------------------------------------------------------------------------
// prep: out[r,t] = silu( sum_d (src[r,d]+bias2[r%64,d]) * W[t,d] + bias[t] )
// rows r = b*64+m (512), cols t (256). Tile 64x64, K-chunks of 32.
// blockIdx.z: 0 -> c (Wc), 1 -> vc (Wv)
__global__ void __launch_bounds__(256) k_prep(
    const float* __restrict__ clusters, const float* __restrict__ cbias,
    const float* __restrict__ Wc, const float* __restrict__ bc,
    const float* __restrict__ vclusters, const float* __restrict__ vbias,
    const float* __restrict__ Wv, const float* __restrict__ bv)
{
    __shared__ float As[64][33];
    __shared__ float Ws[64][33];
    int which = blockIdx.z;
    const float* src   = which ? vclusters : clusters;
    const float* sbias = which ? vbias     : cbias;
    const float* Wp    = which ? Wv        : Wc;
    const float* bo    = which ? bv        : bc;
    float* out         = which ? g_vc      : g_c;

    int r0 = blockIdx.y * 64;   // = b*64, so local row == m
    int t0 = blockIdx.x * 64;
    int tid = threadIdx.x;
    int tx = tid & 15, ty = tid >> 4;

    float acc[4][4] = {};
    for (int k0 = 0; k0 < D; k0 += 32) {
        #pragma unroll
        for (int r = 0; r < 8; r++) {
            int idx = tid + 256*r;
            int row = idx >> 5, kk = idx & 31;
            As[row][kk] = src[(r0+row)*D + k0 + kk] + sbias[row*D + k0 + kk];
            Ws[row][kk] = Wp[(t0+row)*D + k0 + kk];
        }
        __syncthreads();
        #pragma unroll
        for (int k = 0; k < 32; k++) {
            float a[4], w[4];
            #pragma unroll
            for (int i = 0; i < 4; i++) a[i] = As[ty*4+i][k];
            #pragma unroll
            for (int j = 0; j < 4; j++) w[j] = Ws[tx*4+j][k];
            #pragma unroll
            for (int i = 0; i < 4; i++)
                #pragma unroll
                for (int j = 0; j < 4; j++) acc[i][j] += a[i]*w[j];
        }
        __syncthreads();
    }
    #pragma unroll
    for (int i = 0; i < 4; i++)
        #pragma unroll
        for (int j = 0; j < 4; j++) {
            int t = t0 + tx*4 + j;
            float s = acc[i][j] + bo[t];
            float sv = s / (1.f + __expf(-s));   // silu
            out[(r0 + ty*4 + i)*D + t] = sv;
        }
}

// ---------------------------------------------------------------------------
// normalize c rows over D (l2norm with NORM_EPS=1e-12), in place
__global__ void __launch_bounds__(256) k_norm() {
    int r = blockIdx.x;
    int tid = threadIdx.x;
    float v = g_c[r*D + tid];
    float s = v*v;
    #pragma unroll
    for (int o = 16; o > 0; o >>= 1) s += __shfl_xor_sync(0xffffffffu, s, o);
    __shared__ float ws[8];
    if ((tid & 31) == 0) ws[tid >> 5] = s;
    __syncthreads();
    float tot = 0.f;
    #pragma unroll
    for (int w = 0; w < 8; w++) tot += ws[w];
    float inv = 1.f / fmaxf(sqrtf(tot), 1e-12f);
    g_c[r*D + tid] = v * inv;
}

// ---------------------------------------------------------------------------
// sim = cnorm @ points (per b), fuse point-norm, alpha/beta, softmax over M,
// write assignment + accumulate colsum.
// Tile: M=64 x Nt=256, K=256 in chunks of 32. 256 thr, per-thread 8m x 8n.
__global__ void __launch_bounds__(256) k_sim(
    const float* __restrict__ points,
    const float* __restrict__ alpha, const float* __restrict__ beta)
{
    __shared__ float As[64][33];     // cnorm tile  (reused as 'red' in epilogue)
    __shared__ float Bs[32][256];    // points tile (reused as 'pinv' in epilogue)
    int b  = blockIdx.y;
    int n0 = blockIdx.x * 256;
    int tid = threadIdx.x, tx = tid & 31, ty = tid >> 5;

    const float* cn = g_c + b*M*D;
    const float* pp = points + (size_t)b*D*NN;

    float acc[8][8] = {};
    float ss = 0.f;  // sum of squares for column tid

    for (int k0 = 0; k0 < D; k0 += 32) {
        #pragma unroll
        for (int r = 0; r < 8; r++) {
            int idx = tid + 256*r;
            As[idx>>5][idx&31] = cn[(idx>>5)*D + k0 + (idx&31)];
        }
        #pragma unroll
        for (int r = 0; r < 8; r++) {
            int idx = tid + 256*r;
            int kk = idx >> 6, n4 = idx & 63;
            *(float4*)&Bs[kk][n4*4] =
                *(const float4*)&pp[(size_t)(k0+kk)*NN + n0 + n4*4];
        }
        __syncthreads();
        // point-norm partial: thread tid owns column tid
        #pragma unroll
        for (int kk = 0; kk < 32; kk++) { float v = Bs[kk][tid]; ss += v*v; }
        #pragma unroll
        for (int k = 0; k < 32; k++) {
            float a[8], bb[8];
            #pragma unroll
            for (int i = 0; i < 8; i++) a[i] = As[ty + 8*i][k];
            #pragma unroll
            for (int j = 0; j < 8; j++) bb[j] = Bs[k][tx + 32*j];
            #pragma unroll
            for (int i = 0; i < 8; i++)
                #pragma unroll
                for (int j = 0; j < 8; j++) acc[i][j] += a[i]*bb[j];
        }
        __syncthreads();
    }

    float* redp  = &As[0][0];   // 8x256 reduce buffer (2112 >= 2048 floats)
    float* pinvp = &Bs[0][0];   // 256 floats
    pinvp[tid] = 1.f / fmaxf(sqrtf(ss), 1e-12f);
    __syncthreads();

    float al[8], be[8];
    #pragma unroll
    for (int i = 0; i < 8; i++) { al[i] = alpha[ty+8*i]; be[i] = beta[ty+8*i]; }
    float pv[8];
    #pragma unroll
    for (int j = 0; j < 8; j++) pv[j] = pinvp[tx + 32*j];
    #pragma unroll
    for (int i = 0; i < 8; i++)
        #pragma unroll
        for (int j = 0; j < 8; j++)
            acc[i][j] = al[i]*(acc[i][j]*pv[j]) + be[i];

    // softmax over m (64): column max via 8-way cross-warp reduce
    __syncthreads();
    #pragma unroll
    for (int j = 0; j < 8; j++) {
        float lm = acc[0][j];
        #pragma unroll
        for (int i = 1; i < 8; i++) lm = fmaxf(lm, acc[i][j]);
        redp[ty*256 + tx + 32*j] = lm;
    }
    __syncthreads();
    float cmax[8];
    #pragma unroll
    for (int j = 0; j < 8; j++) {
        float m0 = redp[tx+32*j];
        #pragma unroll
        for (int t = 1; t < 8; t++) m0 = fmaxf(m0, redp[t*256 + tx+32*j]);
        cmax[j] = m0;
    }
    __syncthreads();
    #pragma unroll
    for (int j = 0; j < 8; j++) {
        float lsum = 0.f;
        #pragma unroll
        for (int i = 0; i < 8; i++) {
            acc[i][j] = __expf(acc[i][j] - cmax[j]);
            lsum += acc[i][j];
        }
        redp[ty*256 + tx + 32*j] = lsum;
    }
    __syncthreads();
    float cinv[8];
    #pragma unroll
    for (int j = 0; j < 8; j++) {
        float s0 = 0.f;
        #pragma unroll
        for (int t = 0; t < 8; t++) s0 += redp[t*256 + tx+32*j];
        cinv[j] = 1.f / s0;
    }

    float* ao = g_assign + (size_t)b*M*NN;
    #pragma unroll
    for (int i = 0; i < 8; i++) {
        int m = ty + 8*i;
        float rs = 0.f;
        #pragma unroll
        for (int j = 0; j < 8; j++) {
            float v = acc[i][j] * cinv[j];
            rs += v;
            ao[(size_t)m*NN + n0 + tx + 32*j] = v;
        }
        #pragma unroll
        for (int o = 16; o > 0; o >>= 1) rs += __shfl_xor_sync(0xffffffffu, rs, o);
        if (tx == 0) atomicAdd(&g_colsum[b*M + m], rs);
    }
}

// ---------------------------------------------------------------------------
// av = assignment @ values (per b). Split-K over N (32 splits of 512).
__global__ void __launch_bounds__(256) k_av(const float* __restrict__ values) {
    __shared__ float As[64][33];
    __shared__ float Vs[32][256];
    int b  = blockIdx.y;
    int n0 = blockIdx.x * 512;
    int tid = threadIdx.x, tx = tid & 31, ty = tid >> 5;

    const float* ap = g_assign + (size_t)b*M*NN;
    const float* vp = values + (size_t)b*NN*D;

    float acc[8][8] = {};
    for (int k0 = 0; k0 < 512; k0 += 32) {
        #pragma unroll
        for (int r = 0; r < 8; r++) {
            int idx = tid + 256*r;
            As[idx>>5][idx&31] = ap[(size_t)(idx>>5)*NN + n0 + k0 + (idx&31)];
        }
        #pragma unroll
        for (int r = 0; r < 8; r++) {
            int idx = tid + 256*r;
            int kk = idx >> 6, d4 = idx & 63;
            *(float4*)&Vs[kk][d4*4] =
                *(const float4*)&vp[(size_t)(n0+k0+kk)*D + d4*4];
        }
        __syncthreads();
        #pragma unroll
        for (int k = 0; k < 32; k++) {
            float a[8], v[8];
            #pragma unroll
            for (int i = 0; i < 8; i++) a[i] = As[ty + 8*i][k];
            #pragma unroll
            for (int j = 0; j < 8; j++) v[j] = Vs[k][tx + 32*j];
            #pragma unroll
            for (int i = 0; i < 8; i++)
                #pragma unroll
                for (int j = 0; j < 8; j++) acc[i][j] += a[i]*v[j];
        }
        __syncthreads();
    }
    #pragma unroll
    for (int i = 0; i < 8; i++)
        #pragma unroll
        for (int j = 0; j < 8; j++)
            atomicAdd(&g_agg[(b*M + ty + 8*i)*D + tx + 32*j], acc[i][j]);
}

// ---------------------------------------------------------------------------
// agg = (vc + av) / (colsum + 1e-7)
__global__ void __launch_bounds__(256) k_agg() {
    int bm = blockIdx.x;
    int d  = threadIdx.x;
    int idx = bm*D + d;
    g_agg[idx] = (g_vc[idx] + g_agg[idx]) / (g_colsum[bm] + 1e-7f);
}

// ---------------------------------------------------------------------------
// x[b,d,n] = sum_m agg[b,m,d] * assignment[b,m,n].  Tile 64d x 128n, K=64.
__global__ void __launch_bounds__(256) k_x(float* __restrict__ x) {
    __shared__ float Ag[64][64];    // [m][d_local]  (reads are warp-broadcast)
    __shared__ float As2[64][128];  // [m][n_local]
    int b  = blockIdx.z;
    int d0 = blockIdx.y * 64;
    int n0 = blockIdx.x * 128;
    int tid = threadIdx.x, tx = tid & 31, ty = tid >> 5;

    const float* gp = g_agg + b*M*D;
    const float* ap = g_assign + (size_t)b*M*NN;

    #pragma unroll
    for (int r = 0; r < 16; r++) {
        int idx = tid + 256*r;
        Ag[idx>>6][idx&63] = gp[(idx>>6)*D + d0 + (idx&63)];
    }
    #pragma unroll
    for (int r = 0; r < 8; r++) {
        int idx = tid + 256*r;
        int k = idx >> 5, n4 = idx & 31;
        *(float4*)&As2[k][n4*4] =
            *(const float4*)&ap[(size_t)k*NN + n0 + n4*4];
    }
    __syncthreads();

    float acc[8][4] = {};
    #pragma unroll
    for (int k = 0; k < 64; k++) {
        float a[8], v[4];
        #pragma unroll
        for (int i = 0; i < 8; i++) a[i] = Ag[k][ty + 8*i];
        #pragma unroll
        for (int j = 0; j < 4; j++) v[j] = As2[k][tx + 32*j];
        #pragma unroll
        for (int i = 0; i < 8; i++)
            #pragma unroll
            for (int j = 0; j < 4; j++) acc[i][j] += a[i]*v[j];
    }
    #pragma unroll
    for (int i = 0; i < 8; i++)
        #pragma unroll
        for (int j = 0; j < 4; j++)
            x[(size_t)(b*D + d0 + ty + 8*i)*NN + n0 + tx + 32*j] = acc[i][j];
}

// ---------------------------------------------------------------------------
extern "C" void kernel_launch(void* const* d_in, const int* in_sizes, int n_in,
                              void* d_out, int out_size) {
    const float* points    = (const float*)d_in[0];
    const float* clusters  = (const float*)d_in[1];
    const float* values    = (const float*)d_in[2];
    const float* vclusters = (const float*)d_in[3];
    const float* alpha     = (const float*)d_in[4];
    const float* beta      = (const float*)d_in[5];
    const float* cbias     = (const float*)d_in[6];
    const float* Wc        = (const float*)d_in[7];
    const float* bc        = (const float*)d_in[8];
    const float* vbias     = (const float*)d_in[9];
    const float* Wv        = (const float*)d_in[10];
    const float* bv        = (const float*)d_in[11];
    float* x = (float*)d_out;

    k_init<<<512, 256>>>();
    k_prep<<<dim3(4, 8, 2), 256>>>(clusters, cbias, Wc, bc,
                                   vclusters, vbias, Wv, bv);
    k_norm<<<512, 256>>>();
    k_sim<<<dim3(NN/256, B), 256>>>(points, alpha, beta);
    k_av<<<dim3(32, B), 256>>>(values);
    k_agg<<<512, 256>>>();
    k_x<<<dim3(NN/128, D/64, B), 256>>>(x);
}

// round 2
// speedup vs baseline: 1.0023x; 1.0023x over previous
#include <cuda_runtime.h>
#include <math.h>

#define B 8
#define M 64
#define D 256
#define NN 16384

typedef unsigned long long ull;

// ---- packed f32x2 helpers (FFMA2 is only reachable via PTX) ----
__device__ __forceinline__ ull pk2(float x, float y) {
    ull r; asm("mov.b64 %0, {%1, %2};" : "=l"(r) : "f"(x), "f"(y)); return r;
}
__device__ __forceinline__ ull pkb(float x) { return pk2(x, x); }
__device__ __forceinline__ void fma2(ull& d, ull a, ull b) {
    asm("fma.rn.f32x2 %0, %1, %2, %0;" : "+l"(d) : "l"(a), "l"(b));
}
__device__ __forceinline__ float2 upk(ull v) {
    float2 f; asm("mov.b64 {%0, %1}, %2;" : "=f"(f.x), "=f"(f.y) : "l"(v)); return f;
}

// ---- scratch (device globals; no allocations allowed) ----
__device__ float g_c[B*M*D];          // c (then normalized in place -> cnorm)
__device__ float g_vc[B*M*D];         // vc
__device__ float g_assign[(size_t)B*M*NN];   // assignment [B,M,N] 33.5MB
__device__ float g_colsum[B*M];       // sum_n assignment
__device__ float g_agg[B*M*D];        // av accum, then agg in place

// ---------------------------------------------------------------------------
// zero accumulators (must run every launch: graph replays)
__global__ void k_init() {
    int idx = blockIdx.x * 256 + threadIdx.x;
    if (idx < B*M*D) g_agg[idx] = 0.f;
    if (idx < B*M)   g_colsum[idx] = 0.f;
}

// ---------------------------------------------------------------------------
// prep: out[r,t] = silu( sum_d (src[r,d]+bias2[r%64,d]) * W[t,d] + bias[t] )
__global__ void __launch_bounds__(256) k_prep(
    const float* __restrict__ clusters, const float* __restrict__ cbias,
    const float* __restrict__ Wc, const float* __restrict__ bc,
    const float* __restrict__ vclusters, const float* __restrict__ vbias,
    const float* __restrict__ Wv, const float* __restrict__ bv)
{
    __shared__ float As[64][33];
    __shared__ float Ws[64][33];
    int which = blockIdx.z;
    const float* src   = which ? vclusters : clusters;
    const float* sbias = which ? vbias     : cbias;
    const float* Wp    = which ? Wv        : Wc;
    const float* bo    = which ? bv        : bc;
    float* out         = which ? g_vc      : g_c;

    int r0 = blockIdx.y * 64;
    int t0 = blockIdx.x * 64;
    int tid = threadIdx.x;
    int tx = tid & 15, ty = tid >> 4;

    float acc[4][4] = {};
    for (int k0 = 0; k0 < D; k0 += 32) {
        #pragma unroll
        for (int r = 0; r < 8; r++) {
            int idx = tid + 256*r;
            int row = idx >> 5, kk = idx & 31;
            As[row][kk] = src[(r0+row)*D + k0 + kk] + sbias[row*D + k0 + kk];
            Ws[row][kk] = Wp[(t0+row)*D + k0 + kk];
        }
        __syncthreads();
        #pragma unroll
        for (int k = 0; k < 32; k++) {
            float a[4], w[4];
            #pragma unroll
            for (int i = 0; i < 4; i++) a[i] = As[ty*4+i][k];
            #pragma unroll
            for (int j = 0; j < 4; j++) w[j] = Ws[tx*4+j][k];
            #pragma unroll
            for (int i = 0; i < 4; i++)
                #pragma unroll
                for (int j = 0; j < 4; j++) acc[i][j] += a[i]*w[j];
        }
        __syncthreads();
    }
    #pragma unroll
    for (int i = 0; i < 4; i++)
        #pragma unroll
        for (int j = 0; j < 4; j++) {
            int t = t0 + tx*4 + j;
            float s = acc[i][j] + bo[t];
            float sv = s / (1.f + __expf(-s));   // silu
            out[(r0 + ty*4 + i)*D + t] = sv;
        }
}

// ---------------------------------------------------------------------------
// normalize c rows over D (l2norm with NORM_EPS=1e-12), in place
__global__ void __launch_bounds__(256) k_norm() {
    int r = blockIdx.x;
    int tid = threadIdx.x;
    float v = g_c[r*D + tid];
    float s = v*v;
    #pragma unroll
    for (int o = 16; o > 0; o >>= 1) s += __shfl_xor_sync(0xffffffffu, s, o);
    __shared__ float ws[8];
    if ((tid & 31) == 0) ws[tid >> 5] = s;
    __syncthreads();
    float tot = 0.f;
    #pragma unroll
    for (int w = 0; w < 8; w++) tot += ws[w];
    float inv = 1.f / fmaxf(sqrtf(tot), 1e-12f);
    g_c[r*D + tid] = v * inv;
}

// ---------------------------------------------------------------------------
// sim = cnorm @ points (per b), fused point-norm + alpha/beta + softmax over M.
// Tile: M=64 x Nt=256, K=256 chunks of 32. 256 thr. f32x2 accumulators:
// thread owns columns n = tx*2 + 64*j + {0,1}, j=0..3 (4 packed pairs) x 8 m.
__global__ void __launch_bounds__(256) k_sim(
    const float* __restrict__ points,
    const float* __restrict__ alpha, const float* __restrict__ beta)
{
    __shared__ __align__(16) float As[64][33];   // cnorm tile (reused as red buf)
    __shared__ __align__(16) float Bs[32][256];  // points tile (reused as pinv)
    int b  = blockIdx.y;
    int n0 = blockIdx.x * 256;
    int tid = threadIdx.x, tx = tid & 31, ty = tid >> 5;

    const float* cn = g_c + b*M*D;
    const float* pp = points + (size_t)b*D*NN;

    ull acc[8][4] = {};
    float ss = 0.f;  // sum of squares for column tid

    for (int k0 = 0; k0 < D; k0 += 32) {
        #pragma unroll
        for (int r = 0; r < 8; r++) {
            int idx = tid + 256*r;
            As[idx>>5][idx&31] = cn[(idx>>5)*D + k0 + (idx&31)];
        }
        #pragma unroll
        for (int r = 0; r < 8; r++) {
            int idx = tid + 256*r;
            int kk = idx >> 6, n4 = idx & 63;
            *(float4*)&Bs[kk][n4*4] =
                *(const float4*)&pp[(size_t)(k0+kk)*NN + n0 + n4*4];
        }
        __syncthreads();
        #pragma unroll
        for (int kk = 0; kk < 32; kk++) { float v = Bs[kk][tid]; ss += v*v; }
        #pragma unroll
        for (int k = 0; k < 32; k++) {
            ull a2[8], b2[4];
            #pragma unroll
            for (int i = 0; i < 8; i++) a2[i] = pkb(As[ty + 8*i][k]);
            #pragma unroll
            for (int j = 0; j < 4; j++) b2[j] = *(const ull*)&Bs[k][tx*2 + 64*j];
            #pragma unroll
            for (int i = 0; i < 8; i++)
                #pragma unroll
                for (int j = 0; j < 4; j++) fma2(acc[i][j], a2[i], b2[j]);
        }
        __syncthreads();
    }

    // unpack: f[i][c], column nc(c) = tx*2 + 64*(c>>1) + (c&1)
    float f[8][8];
    #pragma unroll
    for (int i = 0; i < 8; i++)
        #pragma unroll
        for (int j = 0; j < 4; j++) {
            float2 t = upk(acc[i][j]);
            f[i][2*j] = t.x; f[i][2*j+1] = t.y;
        }

    float* redp  = &As[0][0];   // 8x256 reduce buffer (2112 >= 2048 floats)
    float* pinvp = &Bs[0][0];   // 256 floats
    pinvp[tid] = 1.f / fmaxf(sqrtf(ss), 1e-12f);
    __syncthreads();

    float al[8], be[8];
    #pragma unroll
    for (int i = 0; i < 8; i++) { al[i] = alpha[ty+8*i]; be[i] = beta[ty+8*i]; }
    float pv[8];
    #pragma unroll
    for (int c = 0; c < 8; c++) pv[c] = pinvp[tx*2 + 64*(c>>1) + (c&1)];
    #pragma unroll
    for (int i = 0; i < 8; i++)
        #pragma unroll
        for (int c = 0; c < 8; c++)
            f[i][c] = al[i]*(f[i][c]*pv[c]) + be[i];

    // softmax over m (64): column max via 8-way cross-warp reduce
    __syncthreads();
    #pragma unroll
    for (int c = 0; c < 8; c++) {
        int nc = tx*2 + 64*(c>>1) + (c&1);
        float lm = f[0][c];
        #pragma unroll
        for (int i = 1; i < 8; i++) lm = fmaxf(lm, f[i][c]);
        redp[ty*256 + nc] = lm;
    }
    __syncthreads();
    float cmax[8];
    #pragma unroll
    for (int c = 0; c < 8; c++) {
        int nc = tx*2 + 64*(c>>1) + (c&1);
        float m0 = redp[nc];
        #pragma unroll
        for (int t = 1; t < 8; t++) m0 = fmaxf(m0, redp[t*256 + nc]);
        cmax[c] = m0;
    }
    __syncthreads();
    #pragma unroll
    for (int c = 0; c < 8; c++) {
        int nc = tx*2 + 64*(c>>1) + (c&1);
        float lsum = 0.f;
        #pragma unroll
        for (int i = 0; i < 8; i++) {
            f[i][c] = __expf(f[i][c] - cmax[c]);
            lsum += f[i][c];
        }
        redp[ty*256 + nc] = lsum;
    }
    __syncthreads();
    float cinv[8];
    #pragma unroll
    for (int c = 0; c < 8; c++) {
        int nc = tx*2 + 64*(c>>1) + (c&1);
        float s0 = 0.f;
        #pragma unroll
        for (int t = 0; t < 8; t++) s0 += redp[t*256 + nc];
        cinv[c] = 1.f / s0;
    }

    float* ao = g_assign + (size_t)b*M*NN;
    #pragma unroll
    for (int i = 0; i < 8; i++) {
        int m = ty + 8*i;
        float rs = 0.f;
        #pragma unroll
        for (int j = 0; j < 4; j++) {
            float v0 = f[i][2*j]   * cinv[2*j];
            float v1 = f[i][2*j+1] * cinv[2*j+1];
            rs += v0 + v1;
            float2 st; st.x = v0; st.y = v1;
            *(float2*)&ao[(size_t)m*NN + n0 + tx*2 + 64*j] = st;
        }
        #pragma unroll
        for (int o = 16; o > 0; o >>= 1) rs += __shfl_xor_sync(0xffffffffu, rs, o);
        if (tx == 0) atomicAdd(&g_colsum[b*M + m], rs);
    }
}

// ---------------------------------------------------------------------------
// av = assignment @ values (per b). Split-K over N (32 splits of 512). f32x2.
__global__ void __launch_bounds__(256) k_av(const float* __restrict__ values) {
    __shared__ __align__(16) float As[64][33];
    __shared__ __align__(16) float Vs[32][256];
    int b  = blockIdx.y;
    int n0 = blockIdx.x * 512;
    int tid = threadIdx.x, tx = tid & 31, ty = tid >> 5;

    const float* ap = g_assign + (size_t)b*M*NN;
    const float* vp = values + (size_t)b*NN*D;

    ull acc[8][4] = {};
    for (int k0 = 0; k0 < 512; k0 += 32) {
        #pragma unroll
        for (int r = 0; r < 8; r++) {
            int idx = tid + 256*r;
            As[idx>>5][idx&31] = ap[(size_t)(idx>>5)*NN + n0 + k0 + (idx&31)];
        }
        #pragma unroll
        for (int r = 0; r < 8; r++) {
            int idx = tid + 256*r;
            int kk = idx >> 6, d4 = idx & 63;
            *(float4*)&Vs[kk][d4*4] =
                *(const float4*)&vp[(size_t)(n0+k0+kk)*D + d4*4];
        }
        __syncthreads();
        #pragma unroll
        for (int k = 0; k < 32; k++) {
            ull a2[8], v2[4];
            #pragma unroll
            for (int i = 0; i < 8; i++) a2[i] = pkb(As[ty + 8*i][k]);
            #pragma unroll
            for (int j = 0; j < 4; j++) v2[j] = *(const ull*)&Vs[k][tx*2 + 64*j];
            #pragma unroll
            for (int i = 0; i < 8; i++)
                #pragma unroll
                for (int j = 0; j < 4; j++) fma2(acc[i][j], a2[i], v2[j]);
        }
        __syncthreads();
    }
    #pragma unroll
    for (int i = 0; i < 8; i++)
        #pragma unroll
        for (int j = 0; j < 4; j++) {
            float2 t = upk(acc[i][j]);
            int base = (b*M + ty + 8*i)*D + tx*2 + 64*j;
            atomicAdd(&g_agg[base],     t.x);
            atomicAdd(&g_agg[base + 1], t.y);
        }
}

// ---------------------------------------------------------------------------
// agg = (vc + av) / (colsum + 1e-7)
__global__ void __launch_bounds__(256) k_agg() {
    int bm = blockIdx.x;
    int d  = threadIdx.x;
    int idx = bm*D + d;
    g_agg[idx] = (g_vc[idx] + g_agg[idx]) / (g_colsum[bm] + 1e-7f);
}

// ---------------------------------------------------------------------------
// x[b,d,n] = sum_m agg[b,m,d] * assignment[b,m,n]. Tile 64d x 128n, K=64.
// f32x2 over the d dimension (contiguous in Ag rows).
__global__ void __launch_bounds__(256) k_x(float* __restrict__ x) {
    __shared__ __align__(16) float Ag[64][64];    // [m][d_local]
    __shared__ __align__(16) float As2[64][128];  // [m][n_local]
    int b  = blockIdx.z;
    int d0 = blockIdx.y * 64;
    int n0 = blockIdx.x * 128;
    int tid = threadIdx.x, tx = tid & 31, ty = tid >> 5;

    const float* gp = g_agg + b*M*D;
    const float* ap = g_assign + (size_t)b*M*NN;

    #pragma unroll
    for (int r = 0; r < 16; r++) {
        int idx = tid + 256*r;
        Ag[idx>>6][idx&63] = gp[(idx>>6)*D + d0 + (idx&63)];
    }
    #pragma unroll
    for (int r = 0; r < 8; r++) {
        int idx = tid + 256*r;
        int k = idx >> 5, n4 = idx & 31;
        *(float4*)&As2[k][n4*4] =
            *(const float4*)&ap[(size_t)k*NN + n0 + n4*4];
    }
    __syncthreads();

    // thread owns d pairs dl = ty*2 + 16*i + {0,1}, i=0..3; n = tx + 32*j, j=0..3
    ull acc[4][4] = {};
    #pragma unroll
    for (int k = 0; k < 64; k++) {
        ull a2[4], b2[4];
        #pragma unroll
        for (int i = 0; i < 4; i++) a2[i] = *(const ull*)&Ag[k][ty*2 + 16*i];
        #pragma unroll
        for (int j = 0; j < 4; j++) b2[j] = pkb(As2[k][tx + 32*j]);
        #pragma unroll
        for (int i = 0; i < 4; i++)
            #pragma unroll
            for (int j = 0; j < 4; j++) fma2(acc[i][j], a2[i], b2[j]);
    }
    #pragma unroll
    for (int i = 0; i < 4; i++) {
        int dl = ty*2 + 16*i;
        #pragma unroll
        for (int j = 0; j < 4; j++) {
            float2 t = upk(acc[i][j]);
            int n = n0 + tx + 32*j;
            x[(size_t)(b*D + d0 + dl    )*NN + n] = t.x;
            x[(size_t)(b*D + d0 + dl + 1)*NN + n] = t.y;
        }
    }
}

// ---------------------------------------------------------------------------
extern "C" void kernel_launch(void* const* d_in, const int* in_sizes, int n_in,
                              void* d_out, int out_size) {
    const float* points    = (const float*)d_in[0];
    const float* clusters  = (const float*)d_in[1];
    const float* values    = (const float*)d_in[2];
    const float* vclusters = (const float*)d_in[3];
    const float* alpha     = (const float*)d_in[4];
    const float* beta      = (const float*)d_in[5];
    const float* cbias     = (const float*)d_in[6];
    const float* Wc        = (const float*)d_in[7];
    const float* bc        = (const float*)d_in[8];
    const float* vbias     = (const float*)d_in[9];
    const float* Wv        = (const float*)d_in[10];
    const float* bv        = (const float*)d_in[11];
    float* x = (float*)d_out;

    k_init<<<512, 256>>>();
    k_prep<<<dim3(4, 8, 2), 256>>>(clusters, cbias, Wc, bc,
                                   vclusters, vbias, Wv, bv);
    k_norm<<<512, 256>>>();
    k_sim<<<dim3(NN/256, B), 256>>>(points, alpha, beta);
    k_av<<<dim3(32, B), 256>>>(values);
    k_agg<<<512, 256>>>();
    k_x<<<dim3(NN/128, D/64, B), 256>>>(x);
}